// round 4
// baseline (speedup 1.0000x reference)
#include <cuda_runtime.h>
#include <cuda_bf16.h>
#include <math.h>

// Problem constants
#define BATCH 16
#define SEQ   512
#define HID   768
#define NT    9
#define DIM   64
#define COUT  (NT * 2 * DIM)   // 1152
#define MROWS (BATCH * SEQ)    // 8192

// Scratch (device globals — no allocation allowed in kernel_launch)
__device__ float g_q[BATCH * NT * SEQ * DIM];   // [b,t,s,d]
__device__ float g_k[BATCH * NT * SEQ * DIM];   // [b,t,s,d]
__device__ float g_cs[SEQ * DIM];               // repeated cos table
__device__ float g_sn[SEQ * DIM];               // repeated sin table

// ---------------------------------------------------------------------------
// Kernel 0: RoPE cos/sin tables.  cos_rep[s][d] = cos(s * 10000^{-2*(d/2)/64})
// ---------------------------------------------------------------------------
__global__ void rope_table() {
    int idx = blockIdx.x * blockDim.x + threadIdx.x;   // 0 .. 32767
    if (idx >= SEQ * DIM) return;
    int s = idx >> 6;
    int d = idx & 63;
    int i = d >> 1;
    float inv = powf(10000.0f, -(float)(2 * i) / 64.0f);
    float ang = (float)s * inv;
    g_cs[idx] = cosf(ang);
    g_sn[idx] = sinf(ang);
}

// ---------------------------------------------------------------------------
// Kernel 1: SGEMM  out[8192,1152] = hidden @ W + b, fused RoPE epilogue,
// scatter into g_q / g_k with [b,t,s,d] layout.
// Block tile 64(M) x 64(N), K-tile 16, 256 threads, 4x4 microtile.
// ---------------------------------------------------------------------------
__global__ void __launch_bounds__(256) gemm_rope(
    const float* __restrict__ hidden,
    const float* __restrict__ Wm,
    const float* __restrict__ bias)
{
    __shared__ float A_sm[16][68];   // [k][m]  (transposed)
    __shared__ float B_sm[16][68];   // [k][n]

    const int tid = threadIdx.x;
    const int tx  = tid & 15;
    const int ty  = tid >> 4;
    const int c0   = blockIdx.x * 64;
    const int row0 = blockIdx.y * 64;

    float acc[4][4] = {};

    const int am = tid >> 2;          // 0..63  (A load row)
    const int ak = (tid & 3) * 4;     // 0,4,8,12 (A load k-quad)
    const int bk = tid >> 4;          // 0..15  (B load k)
    const int bc = (tid & 15) * 4;    // B load col-quad

    for (int k0 = 0; k0 < HID; k0 += 16) {
        float4 av = *(const float4*)(hidden + (size_t)(row0 + am) * HID + k0 + ak);
        A_sm[ak + 0][am] = av.x;
        A_sm[ak + 1][am] = av.y;
        A_sm[ak + 2][am] = av.z;
        A_sm[ak + 3][am] = av.w;
        float4 bv = *(const float4*)(Wm + (size_t)(k0 + bk) * COUT + c0 + bc);
        *(float4*)&B_sm[bk][bc] = bv;
        __syncthreads();

        #pragma unroll
        for (int k = 0; k < 16; k++) {
            float4 a4 = *(const float4*)&A_sm[k][ty * 4];
            float4 b4 = *(const float4*)&B_sm[k][tx * 4];
            float a[4] = {a4.x, a4.y, a4.z, a4.w};
            float b[4] = {b4.x, b4.y, b4.z, b4.w};
            #pragma unroll
            for (int i = 0; i < 4; i++)
                #pragma unroll
                for (int j = 0; j < 4; j++)
                    acc[i][j] += a[i] * b[j];
        }
        __syncthreads();
    }

    // Epilogue: bias + RoPE (interleaved pairs), scatter to g_q / g_k.
    const int cbase = c0 + tx * 4;
    #pragma unroll
    for (int i = 0; i < 4; i++) {
        int row = row0 + ty * 4 + i;
        int bidx = row >> 9;           // / 512
        int s    = row & 511;
        #pragma unroll
        for (int jp = 0; jp < 4; jp += 2) {
            int c = cbase + jp;                 // even
            int t = c >> 7;                     // / 128
            int r = c & 127;
            int isQ = (r < 64);
            int d = r & 63;                     // even
            float xe = acc[i][jp]     + bias[c];
            float xo = acc[i][jp + 1] + bias[c + 1];
            float cv = g_cs[(s << 6) + d];
            float sv = g_sn[(s << 6) + d];
            float ve = xe * cv - xo * sv;
            float vo = xo * cv + xe * sv;
            float* dst = (isQ ? g_q : g_k)
                       + ((size_t)((bidx * NT + t) * SEQ + s) << 6) + d;
            dst[0] = ve;
            dst[1] = vo;
        }
    }
}

// ---------------------------------------------------------------------------
// Kernel 2: logits[b,t,m,n] = sum_d q[b,t,m,d]*k[b,t,n,d], masked, /8.
// Grid (n-tiles=8, m-tiles=8, z=b*9+t=144). Block tile 64x64, K=64 full.
// ---------------------------------------------------------------------------
__global__ void __launch_bounds__(256) qk_kernel(
    const int* __restrict__ amask,
    float* __restrict__ out)
{
    __shared__ float Qt[64][68];   // [d][m]
    __shared__ float Kt[64][68];   // [d][n]

    const int z    = blockIdx.z;        // b*9 + t
    const int bidx = z / NT;
    const int n0   = blockIdx.x * 64;
    const int m0   = blockIdx.y * 64;
    const int tid  = threadIdx.x;
    const int tx   = tid & 15;
    const int ty   = tid >> 4;

    // Load 64x64 Q and K tiles, transposing into [d][row] layout.
    #pragma unroll
    for (int r = 0; r < 4; r++) {
        int e  = r * 256 + tid;
        int mm = e >> 4;
        int dq = (e & 15) * 4;
        float4 qv = *(const float4*)(g_q + ((size_t)(z * SEQ + m0 + mm) << 6) + dq);
        Qt[dq + 0][mm] = qv.x;
        Qt[dq + 1][mm] = qv.y;
        Qt[dq + 2][mm] = qv.z;
        Qt[dq + 3][mm] = qv.w;
        float4 kv = *(const float4*)(g_k + ((size_t)(z * SEQ + n0 + mm) << 6) + dq);
        Kt[dq + 0][mm] = kv.x;
        Kt[dq + 1][mm] = kv.y;
        Kt[dq + 2][mm] = kv.z;
        Kt[dq + 3][mm] = kv.w;
    }
    __syncthreads();

    float acc[4][4] = {};
    #pragma unroll 16
    for (int d = 0; d < 64; d++) {
        float4 a4 = *(const float4*)&Qt[d][ty * 4];
        float4 b4 = *(const float4*)&Kt[d][tx * 4];
        float a[4] = {a4.x, a4.y, a4.z, a4.w};
        float b[4] = {b4.x, b4.y, b4.z, b4.w};
        #pragma unroll
        for (int i = 0; i < 4; i++)
            #pragma unroll
            for (int j = 0; j < 4; j++)
                acc[i][j] += a[i] * b[j];
    }

    // Epilogue: padding mask, strict-lower-triangular mask, scale by 1/8.
    const float NEGC = 1000000000000.0f;
    float pm[4];
    #pragma unroll
    for (int j = 0; j < 4; j++)
        pm[j] = (float)amask[(bidx << 9) + n0 + tx * 4 + j];

    #pragma unroll
    for (int i = 0; i < 4; i++) {
        int m = m0 + ty * 4 + i;
        float4 o;
        float v[4];
        #pragma unroll
        for (int j = 0; j < 4; j++) {
            int n = n0 + tx * 4 + j;
            float val = acc[i][j] * pm[j] - (1.0f - pm[j]) * NEGC;
            if (m > n) val -= NEGC;     // tril(ones, -1)
            v[j] = val * 0.125f;        // / sqrt(64)
        }
        o.x = v[0]; o.y = v[1]; o.z = v[2]; o.w = v[3];
        *(float4*)(out + ((size_t)z * SEQ + m) * SEQ + n0 + tx * 4) = o;
    }
}

// ---------------------------------------------------------------------------
extern "C" void kernel_launch(void* const* d_in, const int* in_sizes, int n_in,
                              void* d_out, int out_size)
{
    const float* hidden = (const float*)d_in[0];
    const float* Wm     = (const float*)d_in[1];
    const float* bias   = (const float*)d_in[2];
    const int*   amask  = (const int*)d_in[3];
    float* out = (float*)d_out;

    rope_table<<<(SEQ * DIM + 255) / 256, 256>>>();
    gemm_rope<<<dim3(COUT / 64, MROWS / 64), 256>>>(hidden, Wm, bias);
    qk_kernel<<<dim3(SEQ / 64, SEQ / 64, BATCH * NT), 256>>>(amask, out);
}

// round 9
// speedup vs baseline: 3.2530x; 3.2530x over previous
#include <cuda_runtime.h>
#include <cuda_bf16.h>
#include <math.h>

// Problem constants
#define BATCH 16
#define SEQ   512
#define HID   768
#define NT    9
#define DIM   64
#define COUT  (NT * 2 * DIM)   // 1152
#define MROWS (BATCH * SEQ)    // 8192
#define NEGC  1000000000000.0f

// Scratch (device globals — no allocation allowed in kernel_launch)
__device__ __align__(16) __nv_bfloat16 g_q[BATCH * NT * SEQ * DIM];  // [b,t,s,d] bf16
__device__ __align__(16) __nv_bfloat16 g_k[BATCH * NT * SEQ * DIM];  // [b,t,s,d] bf16
__device__ float g_cs[SEQ * DIM];   // repeated cos table
__device__ float g_sn[SEQ * DIM];   // repeated sin table

// ---------------------------------------------------------------------------
// Kernel 0: RoPE cos/sin tables.
// ---------------------------------------------------------------------------
__global__ void rope_table() {
    int idx = blockIdx.x * blockDim.x + threadIdx.x;   // 0 .. 32767
    if (idx >= SEQ * DIM) return;
    int s = idx >> 6;
    int d = idx & 63;
    int i = d >> 1;
    float inv = powf(10000.0f, -(float)(2 * i) / 64.0f);
    float ang = (float)s * inv;
    g_cs[idx] = cosf(ang);
    g_sn[idx] = sinf(ang);
}

// ---------------------------------------------------------------------------
// Helpers
// ---------------------------------------------------------------------------
__device__ __forceinline__ unsigned pk(float lo, float hi) {
    __nv_bfloat162 h = __float22bfloat162_rn(make_float2(lo, hi));
    return *reinterpret_cast<unsigned*>(&h);
}

__device__ __forceinline__ void mma16816(float* c,
    unsigned a0, unsigned a1, unsigned a2, unsigned a3,
    unsigned b0, unsigned b1)
{
    asm volatile(
        "mma.sync.aligned.m16n8k16.row.col.f32.bf16.bf16.f32 "
        "{%0,%1,%2,%3},{%4,%5,%6,%7},{%8,%9},{%0,%1,%2,%3};\n"
        : "+f"(c[0]), "+f"(c[1]), "+f"(c[2]), "+f"(c[3])
        : "r"(a0), "r"(a1), "r"(a2), "r"(a3), "r"(b0), "r"(b1));
}

// ---------------------------------------------------------------------------
// Kernel 1: bf16 tensor-core GEMM  out[8192,1152] = hidden @ W + b,
// fused RoPE epilogue, scatter into g_q / g_k (bf16, [b,t,s,d]).
// Block 128(M) x 128(N), K-tile 32, 256 threads, warp grid 4x2 (32x64/warp).
// smem pitch: A/B 40 halves (20 words) -> conflict-free fragment lds.
// ---------------------------------------------------------------------------
__global__ void __launch_bounds__(256) gemm_rope(
    const float* __restrict__ hidden,
    const float* __restrict__ Wm,
    const float* __restrict__ bias)
{
    __shared__ __align__(16) __nv_bfloat16 As[128 * 40];   // [m][k]  halves
    __shared__ __align__(16) __nv_bfloat16 Bs[128 * 40];   // [n][k]  halves (transposed)
    __shared__ float bias_s[128];

    const int tid  = threadIdx.x;
    const int lane = tid & 31;
    const int warp = tid >> 5;
    const int wm   = warp >> 1;   // 0..3
    const int wn   = warp & 1;    // 0..1
    const int row0 = blockIdx.y * 128;
    const int t    = blockIdx.x;          // one n-tile == one head t
    const int c0   = t * 128;

    if (tid < 128) bias_s[tid] = bias[c0 + tid];

    unsigned* Aw = reinterpret_cast<unsigned*>(As);
    unsigned* Bw = reinterpret_cast<unsigned*>(Bs);

    float4 aSt[4];
    float  bSt[16];

    auto fetch = [&](int k0) {
        #pragma unroll
        for (int it = 0; it < 4; it++) {
            int idx = it * 256 + tid;
            int m = idx >> 3, kq = (idx & 7) << 2;
            aSt[it] = *(const float4*)(hidden + (size_t)(row0 + m) * HID + k0 + kq);
        }
        #pragma unroll
        for (int it = 0; it < 8; it++) {
            int idx = it * 256 + tid;
            int n = idx & 127, kp = idx >> 7;           // kp 0..15 (pair of k rows)
            const float* p = Wm + (size_t)(k0 + 2 * kp) * COUT + c0 + n;
            bSt[2 * it]     = p[0];
            bSt[2 * it + 1] = p[COUT];
        }
    };
    auto commit = [&]() {
        #pragma unroll
        for (int it = 0; it < 4; it++) {
            int idx = it * 256 + tid;
            int m = idx >> 3, kq = (idx & 7) << 2;
            int w = m * 20 + (kq >> 1);
            Aw[w]     = pk(aSt[it].x, aSt[it].y);
            Aw[w + 1] = pk(aSt[it].z, aSt[it].w);
        }
        #pragma unroll
        for (int it = 0; it < 8; it++) {
            int idx = it * 256 + tid;
            int n = idx & 127, kp = idx >> 7;
            Bw[n * 20 + kp] = pk(bSt[2 * it], bSt[2 * it + 1]);
        }
    };

    float acc[2][8][4] = {};

    fetch(0);
    for (int kt = 0; kt < HID / 32; kt++) {
        commit();
        __syncthreads();
        if (kt + 1 < HID / 32) fetch((kt + 1) * 32);

        #pragma unroll
        for (int ks = 0; ks < 2; ks++) {
            unsigned af[2][4];
            #pragma unroll
            for (int mi = 0; mi < 2; mi++) {
                int base = (wm * 32 + mi * 16 + (lane >> 2)) * 20 + ks * 8 + (lane & 3);
                af[mi][0] = Aw[base];
                af[mi][1] = Aw[base + 160];   // +8 rows
                af[mi][2] = Aw[base + 4];     // k+8
                af[mi][3] = Aw[base + 164];
            }
            #pragma unroll
            for (int ni = 0; ni < 8; ni++) {
                int n = wn * 64 + ni * 8 + (lane >> 2);
                int base = n * 20 + ks * 8 + (lane & 3);
                unsigned b0 = Bw[base], b1 = Bw[base + 4];
                mma16816(acc[0][ni], af[0][0], af[0][1], af[0][2], af[0][3], b0, b1);
                mma16816(acc[1][ni], af[1][0], af[1][1], af[1][2], af[1][3], b0, b1);
            }
        }
        __syncthreads();
    }

    // Epilogue: bias + RoPE (interleaved pairs live in c-reg pairs), store bf16x2.
    const int r     = lane >> 2;
    const int cpair = 2 * (lane & 3);
    #pragma unroll
    for (int mi = 0; mi < 2; mi++) {
        #pragma unroll
        for (int half = 0; half < 2; half++) {            // rows r / r+8
            int ml  = wm * 32 + mi * 16 + r + half * 8;
            int row = row0 + ml;
            int bb  = row >> 9;
            int s   = row & 511;
            #pragma unroll
            for (int ni = 0; ni < 8; ni++) {
                int cl = wn * 64 + ni * 8 + cpair;        // 0..127, even
                float xe = acc[mi][ni][half * 2 + 0] + bias_s[cl];
                float xo = acc[mi][ni][half * 2 + 1] + bias_s[cl + 1];
                int d = cl & 63;
                float cv = g_cs[(s << 6) + d];
                float sv = g_sn[(s << 6) + d];
                float ve = xe * cv - xo * sv;
                float vo = xo * cv + xe * sv;
                __nv_bfloat16* dst = ((cl < 64) ? g_q : g_k)
                                   + ((size_t)((bb * NT + t) * SEQ + s) << 6) + d;
                *reinterpret_cast<unsigned*>(dst) = pk(ve, vo);
            }
        }
    }
}

// ---------------------------------------------------------------------------
// Kernel 2: logits[b,t,m,n] = q . k over d=64, bf16 tensor cores,
// fused mask / tril / scale epilogue.  Block 128x128, grid (4,4,144).
// smem pitch 72 halves (36 words) -> conflict-free fragment lds.
// ---------------------------------------------------------------------------
__global__ void __launch_bounds__(256) qk_kernel(
    const int* __restrict__ amask,
    float* __restrict__ out)
{
    __shared__ __align__(16) __nv_bfloat16 Qs[128 * 72];
    __shared__ __align__(16) __nv_bfloat16 Ks[128 * 72];
    __shared__ float pm_s[128];

    const int tid  = threadIdx.x;
    const int lane = tid & 31;
    const int warp = tid >> 5;
    const int wm   = warp >> 1;
    const int wn   = warp & 1;
    const int z    = blockIdx.z;          // b*9 + t
    const int bb   = z / NT;
    const int n0   = blockIdx.x * 128;
    const int m0   = blockIdx.y * 128;

    #pragma unroll
    for (int it = 0; it < 4; it++) {
        int idx = it * 256 + tid;
        int m = idx >> 3, dq = (idx & 7) << 3;           // 8 halves per uint4
        *(uint4*)&Qs[m * 72 + dq] = *(const uint4*)(g_q + ((size_t)(z * SEQ + m0 + m) << 6) + dq);
        *(uint4*)&Ks[m * 72 + dq] = *(const uint4*)(g_k + ((size_t)(z * SEQ + n0 + m) << 6) + dq);
    }
    if (tid < 128) pm_s[tid] = (float)amask[(bb << 9) + n0 + tid];
    __syncthreads();

    const unsigned* Qw = reinterpret_cast<const unsigned*>(Qs);
    const unsigned* Kw = reinterpret_cast<const unsigned*>(Ks);

    float acc[2][8][4] = {};
    #pragma unroll
    for (int ks = 0; ks < 4; ks++) {
        unsigned af[2][4];
        #pragma unroll
        for (int mi = 0; mi < 2; mi++) {
            int base = (wm * 32 + mi * 16 + (lane >> 2)) * 36 + ks * 8 + (lane & 3);
            af[mi][0] = Qw[base];
            af[mi][1] = Qw[base + 288];   // +8 rows
            af[mi][2] = Qw[base + 4];     // k+8
            af[mi][3] = Qw[base + 292];
        }
        #pragma unroll
        for (int ni = 0; ni < 8; ni++) {
            int n = wn * 64 + ni * 8 + (lane >> 2);
            int base = n * 36 + ks * 8 + (lane & 3);
            unsigned b0 = Kw[base], b1 = Kw[base + 4];
            mma16816(acc[0][ni], af[0][0], af[0][1], af[0][2], af[0][3], b0, b1);
            mma16816(acc[1][ni], af[1][0], af[1][1], af[1][2], af[1][3], b0, b1);
        }
    }

    // Epilogue: padding mask, strict-lower-tril, /8.
    const int r     = lane >> 2;
    const int cpair = 2 * (lane & 3);
    #pragma unroll
    for (int mi = 0; mi < 2; mi++) {
        #pragma unroll
        for (int half = 0; half < 2; half++) {
            int m = m0 + wm * 32 + mi * 16 + r + half * 8;
            #pragma unroll
            for (int ni = 0; ni < 8; ni++) {
                int nl = wn * 64 + ni * 8 + cpair;
                int n  = n0 + nl;
                float p0 = pm_s[nl], p1 = pm_s[nl + 1];
                float v0 = acc[mi][ni][half * 2 + 0] * p0 - (1.0f - p0) * NEGC;
                float v1 = acc[mi][ni][half * 2 + 1] * p1 - (1.0f - p1) * NEGC;
                if (m > n)     v0 -= NEGC;
                if (m > n + 1) v1 -= NEGC;
                v0 *= 0.125f;
                v1 *= 0.125f;
                *(float2*)(out + ((size_t)z * SEQ + m) * SEQ + n) = make_float2(v0, v1);
            }
        }
    }
}

// ---------------------------------------------------------------------------
extern "C" void kernel_launch(void* const* d_in, const int* in_sizes, int n_in,
                              void* d_out, int out_size)
{
    const float* hidden = (const float*)d_in[0];
    const float* Wm     = (const float*)d_in[1];
    const float* bias   = (const float*)d_in[2];
    const int*   amask  = (const int*)d_in[3];
    float* out = (float*)d_out;

    rope_table<<<(SEQ * DIM + 255) / 256, 256>>>();
    gemm_rope<<<dim3(COUT / 128, MROWS / 128), 256>>>(hidden, Wm, bias);
    qk_kernel<<<dim3(SEQ / 128, SEQ / 128, BATCH * NT), 256>>>(amask, out);
}

// round 11
// speedup vs baseline: 4.3565x; 1.3393x over previous
#include <cuda_runtime.h>
#include <cuda_bf16.h>
#include <math.h>

// Problem constants
#define BATCH 16
#define SEQ   512
#define HID   768
#define NT    9
#define DIM   64
#define COUT  (NT * 2 * DIM)   // 1152
#define MROWS (BATCH * SEQ)    // 8192
#define NEGC  1000000000000.0f

#define PA 20   // smem pitch in 32-bit words, gemm_rope tiles (40 halves)
#define PQ 36   // smem pitch in 32-bit words, qk tiles (72 halves)

// Scratch (device globals — no allocation allowed in kernel_launch)
__device__ __align__(16) __nv_bfloat16 g_q[BATCH * NT * SEQ * DIM];  // [b,t,s,d]
__device__ __align__(16) __nv_bfloat16 g_k[BATCH * NT * SEQ * DIM];  // [b,t,s,d]
__device__ float g_cs[SEQ * DIM];
__device__ float g_sn[SEQ * DIM];

// ---------------------------------------------------------------------------
// Kernel 0: RoPE cos/sin tables.
// ---------------------------------------------------------------------------
__global__ void rope_table() {
    int idx = blockIdx.x * blockDim.x + threadIdx.x;
    if (idx >= SEQ * DIM) return;
    int s = idx >> 6;
    int d = idx & 63;
    int i = d >> 1;
    float inv = powf(10000.0f, -(float)(2 * i) / 64.0f);
    float ang = (float)s * inv;
    g_cs[idx] = cosf(ang);
    g_sn[idx] = sinf(ang);
}

// ---------------------------------------------------------------------------
// Helpers
// ---------------------------------------------------------------------------
__device__ __forceinline__ unsigned pk(float lo, float hi) {
    __nv_bfloat162 h = __float22bfloat162_rn(make_float2(lo, hi));
    return *reinterpret_cast<unsigned*>(&h);
}

__device__ __forceinline__ unsigned smem_u32(const void* p) {
    return (unsigned)__cvta_generic_to_shared(p);
}

__device__ __forceinline__ void ldsm4(unsigned r[4], unsigned addr) {
    asm volatile("ldmatrix.sync.aligned.m8n8.x4.shared.b16 {%0,%1,%2,%3}, [%4];"
                 : "=r"(r[0]), "=r"(r[1]), "=r"(r[2]), "=r"(r[3]) : "r"(addr));
}

__device__ __forceinline__ void mma16816(float* c,
    unsigned a0, unsigned a1, unsigned a2, unsigned a3,
    unsigned b0, unsigned b1)
{
    asm volatile(
        "mma.sync.aligned.m16n8k16.row.col.f32.bf16.bf16.f32 "
        "{%0,%1,%2,%3},{%4,%5,%6,%7},{%8,%9},{%0,%1,%2,%3};\n"
        : "+f"(c[0]), "+f"(c[1]), "+f"(c[2]), "+f"(c[3])
        : "r"(a0), "r"(a1), "r"(a2), "r"(a3), "r"(b0), "r"(b1));
}

// ---------------------------------------------------------------------------
// Kernel 1: bf16 tensor-core GEMM  out[8192,1152] = hidden @ W + b,
// fused RoPE epilogue, scatter into g_q / g_k (bf16, [b,t,s,d]).
// Block 128x128, K-tile 32, 256 threads, warps 4x2, double-buffered smem,
// ldmatrix fragment loads.
// ---------------------------------------------------------------------------
__global__ void __launch_bounds__(256) gemm_rope(
    const float* __restrict__ hidden,
    const float* __restrict__ Wm,
    const float* __restrict__ bias)
{
    __shared__ __align__(16) __nv_bfloat16 As[2][128 * 2 * PA];
    __shared__ __align__(16) __nv_bfloat16 Bs[2][128 * 2 * PA];
    __shared__ float bias_s[128];

    const int tid  = threadIdx.x;
    const int lane = tid & 31;
    const int warp = tid >> 5;
    const int wm   = warp >> 1;
    const int wn   = warp & 1;
    const int row0 = blockIdx.y * 128;
    const int t    = blockIdx.x;
    const int c0   = t * 128;

    if (tid < 128) bias_s[tid] = bias[c0 + tid];

    const int grp = lane >> 3;
    const int lr  = lane & 7;

    // ldmatrix base addresses (bytes, shared space), per buffer.
    // A matrices: (m0-7,k0-7),(m8-15,k0-7),(m0-7,k8-15),(m8-15,k8-15) -> a0..a3
    // B matrices: (n0-7,k0-7),(n0-7,k8-15),(n8-15,k0-7),(n8-15,k8-15) -> b0,b1,b0',b1'
    unsigned aB[2], bB[2];
    #pragma unroll
    for (int s = 0; s < 2; s++) {
        aB[s] = smem_u32(&As[s][0]) +
                ((unsigned)((wm * 32 + (grp & 1) * 8 + lr) * PA + (grp >> 1) * 4) << 2);
        bB[s] = smem_u32(&Bs[s][0]) +
                ((unsigned)((wn * 64 + (grp >> 1) * 8 + lr) * PA + (grp & 1) * 4) << 2);
    }

    float4 aSt[4];
    float  bSt[16];

    auto fetch = [&](int k0) {
        #pragma unroll
        for (int it = 0; it < 4; it++) {
            int idx = it * 256 + tid;
            int m = idx >> 3, kq = (idx & 7) << 2;
            aSt[it] = *(const float4*)(hidden + (size_t)(row0 + m) * HID + k0 + kq);
        }
        #pragma unroll
        for (int it = 0; it < 8; it++) {
            int idx = it * 256 + tid;
            int n = idx & 127, kp = idx >> 7;
            const float* p = Wm + (size_t)(k0 + 2 * kp) * COUT + c0 + n;
            bSt[2 * it]     = p[0];
            bSt[2 * it + 1] = p[COUT];
        }
    };
    auto commit = [&](int s) {
        unsigned* Aw = reinterpret_cast<unsigned*>(As[s]);
        unsigned* Bw = reinterpret_cast<unsigned*>(Bs[s]);
        #pragma unroll
        for (int it = 0; it < 4; it++) {
            int idx = it * 256 + tid;
            int m = idx >> 3, kq = (idx & 7) << 2;
            int w = m * PA + (kq >> 1);
            Aw[w]     = pk(aSt[it].x, aSt[it].y);
            Aw[w + 1] = pk(aSt[it].z, aSt[it].w);
        }
        #pragma unroll
        for (int it = 0; it < 8; it++) {
            int idx = it * 256 + tid;
            int n = idx & 127, kp = idx >> 7;
            Bw[n * PA + kp] = pk(bSt[2 * it], bSt[2 * it + 1]);
        }
    };

    float acc[2][8][4] = {};

    fetch(0);
    commit(0);
    __syncthreads();

    const int NKT = HID / 32;   // 24
    for (int kt = 0; kt < NKT; kt++) {
        int cur = kt & 1;
        if (kt + 1 < NKT) fetch((kt + 1) * 32);

        #pragma unroll
        for (int ks = 0; ks < 2; ks++) {
            unsigned af0[4], af1[4];
            ldsm4(af0, aB[cur] + ks * 32);
            ldsm4(af1, aB[cur] + 16 * PA * 4 + ks * 32);
            unsigned bf[4][4];
            #pragma unroll
            for (int pr = 0; pr < 4; pr++)
                ldsm4(bf[pr], bB[cur] + pr * 16 * PA * 4 + ks * 32);
            #pragma unroll
            for (int ni = 0; ni < 8; ni++) {
                unsigned b0 = bf[ni >> 1][(ni & 1) * 2];
                unsigned b1 = bf[ni >> 1][(ni & 1) * 2 + 1];
                mma16816(acc[0][ni], af0[0], af0[1], af0[2], af0[3], b0, b1);
                mma16816(acc[1][ni], af1[0], af1[1], af1[2], af1[3], b0, b1);
            }
        }

        if (kt + 1 < NKT) commit(1 - cur);
        __syncthreads();
    }

    // Epilogue: bias + RoPE (interleaved pairs live in c-reg pairs), store bf16x2.
    const int r     = lane >> 2;
    const int cpair = 2 * (lane & 3);
    #pragma unroll
    for (int mi = 0; mi < 2; mi++) {
        #pragma unroll
        for (int half = 0; half < 2; half++) {
            int ml  = wm * 32 + mi * 16 + r + half * 8;
            int row = row0 + ml;
            int bb  = row >> 9;
            int s   = row & 511;
            #pragma unroll
            for (int ni = 0; ni < 8; ni++) {
                int cl = wn * 64 + ni * 8 + cpair;
                float xe = acc[mi][ni][half * 2 + 0] + bias_s[cl];
                float xo = acc[mi][ni][half * 2 + 1] + bias_s[cl + 1];
                int d = cl & 63;
                float cv = g_cs[(s << 6) + d];
                float sv = g_sn[(s << 6) + d];
                float ve = xe * cv - xo * sv;
                float vo = xo * cv + xe * sv;
                __nv_bfloat16* dst = ((cl < 64) ? g_q : g_k)
                                   + ((size_t)((bb * NT + t) * SEQ + s) << 6) + d;
                *reinterpret_cast<unsigned*>(dst) = pk(ve, vo);
            }
        }
    }
}

// ---------------------------------------------------------------------------
// Kernel 2: logits[b,t,m,n] = q . k over d=64, bf16 tensor cores,
// cp.async smem fill, ldmatrix fragments, fused mask/tril/scale epilogue.
// Block 128x128, grid (4,4,144).
// ---------------------------------------------------------------------------
__global__ void __launch_bounds__(256) qk_kernel(
    const int* __restrict__ amask,
    float* __restrict__ out)
{
    __shared__ __align__(16) __nv_bfloat16 Qs[128 * 2 * PQ];
    __shared__ __align__(16) __nv_bfloat16 Ks[128 * 2 * PQ];
    __shared__ float pm_s[128];

    const int tid  = threadIdx.x;
    const int lane = tid & 31;
    const int warp = tid >> 5;
    const int wm   = warp >> 1;
    const int wn   = warp & 1;
    const int z    = blockIdx.z;          // b*9 + t
    const int bb   = z / NT;
    const int n0   = blockIdx.x * 128;
    const int m0   = blockIdx.y * 128;

    // Async 16B copies: Q/K tiles are raw bf16 moves (no conversion needed).
    #pragma unroll
    for (int it = 0; it < 4; it++) {
        int idx = it * 256 + tid;
        int m = idx >> 3, c = (idx & 7) * 8;          // c: half offset, 16B chunks
        unsigned dq = smem_u32(&Qs[m * 2 * PQ + c]);
        const __nv_bfloat16* sq = g_q + ((size_t)(z * SEQ + m0 + m) << 6) + c;
        asm volatile("cp.async.cg.shared.global [%0], [%1], 16;" :: "r"(dq), "l"(sq));
        unsigned dk = smem_u32(&Ks[m * 2 * PQ + c]);
        const __nv_bfloat16* sk = g_k + ((size_t)(z * SEQ + n0 + m) << 6) + c;
        asm volatile("cp.async.cg.shared.global [%0], [%1], 16;" :: "r"(dk), "l"(sk));
    }
    asm volatile("cp.async.commit_group;");
    if (tid < 128) pm_s[tid] = (float)amask[(bb << 9) + n0 + tid];
    asm volatile("cp.async.wait_group 0;");
    __syncthreads();

    const int grp = lane >> 3;
    const int lr  = lane & 7;
    unsigned aBase = smem_u32(&Qs[0]) +
                     ((unsigned)((wm * 32 + (grp & 1) * 8 + lr) * PQ + (grp >> 1) * 4) << 2);
    unsigned bBase = smem_u32(&Ks[0]) +
                     ((unsigned)((wn * 64 + (grp >> 1) * 8 + lr) * PQ + (grp & 1) * 4) << 2);

    float acc[2][8][4] = {};
    #pragma unroll
    for (int ks = 0; ks < 4; ks++) {
        unsigned af0[4], af1[4];
        ldsm4(af0, aBase + ks * 32);
        ldsm4(af1, aBase + 16 * PQ * 4 + ks * 32);
        unsigned bf[4][4];
        #pragma unroll
        for (int pr = 0; pr < 4; pr++)
            ldsm4(bf[pr], bBase + pr * 16 * PQ * 4 + ks * 32);
        #pragma unroll
        for (int ni = 0; ni < 8; ni++) {
            unsigned b0 = bf[ni >> 1][(ni & 1) * 2];
            unsigned b1 = bf[ni >> 1][(ni & 1) * 2 + 1];
            mma16816(acc[0][ni], af0[0], af0[1], af0[2], af0[3], b0, b1);
            mma16816(acc[1][ni], af1[0], af1[1], af1[2], af1[3], b0, b1);
        }
    }

    // Epilogue: padding mask, strict-lower-tril, /8.
    const int r     = lane >> 2;
    const int cpair = 2 * (lane & 3);
    #pragma unroll
    for (int mi = 0; mi < 2; mi++) {
        #pragma unroll
        for (int half = 0; half < 2; half++) {
            int m = m0 + wm * 32 + mi * 16 + r + half * 8;
            #pragma unroll
            for (int ni = 0; ni < 8; ni++) {
                int nl = wn * 64 + ni * 8 + cpair;
                int n  = n0 + nl;
                float p0 = pm_s[nl], p1 = pm_s[nl + 1];
                float v0 = acc[mi][ni][half * 2 + 0] * p0 - (1.0f - p0) * NEGC;
                float v1 = acc[mi][ni][half * 2 + 1] * p1 - (1.0f - p1) * NEGC;
                if (m > n)     v0 -= NEGC;
                if (m > n + 1) v1 -= NEGC;
                v0 *= 0.125f;
                v1 *= 0.125f;
                *(float2*)(out + ((size_t)z * SEQ + m) * SEQ + n) = make_float2(v0, v1);
            }
        }
    }
}

// ---------------------------------------------------------------------------
extern "C" void kernel_launch(void* const* d_in, const int* in_sizes, int n_in,
                              void* d_out, int out_size)
{
    const float* hidden = (const float*)d_in[0];
    const float* Wm     = (const float*)d_in[1];
    const float* bias   = (const float*)d_in[2];
    const int*   amask  = (const int*)d_in[3];
    float* out = (float*)d_out;

    rope_table<<<(SEQ * DIM + 255) / 256, 256>>>();
    gemm_rope<<<dim3(COUT / 128, MROWS / 128), 256>>>(hidden, Wm, bias);
    qk_kernel<<<dim3(SEQ / 128, SEQ / 128, BATCH * NT), 256>>>(amask, out);
}

// round 12
// speedup vs baseline: 4.4004x; 1.0101x over previous
#include <cuda_runtime.h>
#include <cuda_bf16.h>
#include <math.h>

// Problem constants
#define BATCH 16
#define SEQ   512
#define HID   768
#define NT    9
#define DIM   64
#define COUT  (NT * 2 * DIM)   // 1152
#define MROWS (BATCH * SEQ)    // 8192
#define NEGC  1000000000000.0f

#define PA 20   // smem pitch in 32-bit words, gemm tiles (40 halves = 80 B, 16B-divisible)
#define PQ 36   // smem pitch in 32-bit words, qk tiles (72 halves = 144 B, 16B-divisible)

// Scratch (device globals — no allocation allowed in kernel_launch)
__device__ __align__(16) __nv_bfloat16 g_q[BATCH * NT * SEQ * DIM];   // [b,t,s,d]
__device__ __align__(16) __nv_bfloat16 g_k[BATCH * NT * SEQ * DIM];   // [b,t,s,d]
__device__ __align__(16) __nv_bfloat16 g_hid[MROWS * HID];            // bf16 hidden [m][k]
__device__ __align__(16) __nv_bfloat16 g_wb[COUT * HID];              // bf16 W^T [n][k]
__device__ float g_cs[SEQ * DIM];
__device__ float g_sn[SEQ * DIM];

// ---------------------------------------------------------------------------
// Helpers
// ---------------------------------------------------------------------------
__device__ __forceinline__ unsigned pk(float lo, float hi) {
    __nv_bfloat162 h = __float22bfloat162_rn(make_float2(lo, hi));
    return *reinterpret_cast<unsigned*>(&h);
}

__device__ __forceinline__ unsigned smem_u32(const void* p) {
    return (unsigned)__cvta_generic_to_shared(p);
}

__device__ __forceinline__ void ldsm4(unsigned r[4], unsigned addr) {
    asm volatile("ldmatrix.sync.aligned.m8n8.x4.shared.b16 {%0,%1,%2,%3}, [%4];"
                 : "=r"(r[0]), "=r"(r[1]), "=r"(r[2]), "=r"(r[3]) : "r"(addr));
}

__device__ __forceinline__ void mma16816(float* c,
    unsigned a0, unsigned a1, unsigned a2, unsigned a3,
    unsigned b0, unsigned b1)
{
    asm volatile(
        "mma.sync.aligned.m16n8k16.row.col.f32.bf16.bf16.f32 "
        "{%0,%1,%2,%3},{%4,%5,%6,%7},{%8,%9},{%0,%1,%2,%3};\n"
        : "+f"(c[0]), "+f"(c[1]), "+f"(c[2]), "+f"(c[3])
        : "r"(a0), "r"(a1), "r"(a2), "r"(a3), "r"(b0), "r"(b1));
}

// ---------------------------------------------------------------------------
// Kernel 0 (prep): hidden -> bf16, W -> bf16 transposed [n][k], RoPE tables.
// ---------------------------------------------------------------------------
#define HQ (MROWS * HID / 4)   // 1,572,864 float4 quads of hidden
#define WQ (COUT * HID / 4)    //   221,184 (n, k-quad) pairs of W
#define PREP_TOT (HQ + WQ + SEQ * DIM)   // 1,826,816 = 7136 * 256

__global__ void __launch_bounds__(256) prep(
    const float* __restrict__ hidden,
    const float* __restrict__ Wm)
{
    int idx = blockIdx.x * blockDim.x + threadIdx.x;
    if (idx < HQ) {
        float4 v = ((const float4*)hidden)[idx];
        uint2 o = make_uint2(pk(v.x, v.y), pk(v.z, v.w));
        *reinterpret_cast<uint2*>(g_hid + (size_t)idx * 4) = o;
    } else if (idx < HQ + WQ) {
        int j  = idx - HQ;
        int n  = j % COUT;          // consecutive threads -> consecutive n (coalesced reads)
        int kq = j / COUT;
        int k  = kq * 4;
        float a = Wm[(size_t)(k + 0) * COUT + n];
        float b = Wm[(size_t)(k + 1) * COUT + n];
        float c = Wm[(size_t)(k + 2) * COUT + n];
        float d = Wm[(size_t)(k + 3) * COUT + n];
        uint2 o = make_uint2(pk(a, b), pk(c, d));
        *reinterpret_cast<uint2*>(g_wb + (size_t)n * HID + k) = o;
    } else if (idx < PREP_TOT) {
        int e = idx - HQ - WQ;
        int s = e >> 6, d = e & 63, i = d >> 1;
        float inv = powf(10000.0f, -(float)(2 * i) / 64.0f);
        float ang = (float)s * inv;
        g_cs[e] = cosf(ang);
        g_sn[e] = sinf(ang);
    }
}

// ---------------------------------------------------------------------------
// Kernel 1: bf16 tensor-core GEMM  out[8192,1152] = hidden @ W + b,
// fused RoPE epilogue, scatter into g_q / g_k (bf16, [b,t,s,d]).
// Block 128x128, K-tile 32, 256 threads, warps 4x2, double-buffered smem,
// register-staged prefetch, ldmatrix fragment loads, bf16 operands from prep.
// ---------------------------------------------------------------------------
__global__ void __launch_bounds__(256) gemm_rope(const float* __restrict__ bias)
{
    __shared__ __align__(16) __nv_bfloat16 As[2][128 * 2 * PA];
    __shared__ __align__(16) __nv_bfloat16 Bs[2][128 * 2 * PA];
    __shared__ float bias_s[128];

    const int tid  = threadIdx.x;
    const int lane = tid & 31;
    const int warp = tid >> 5;
    const int wm   = warp >> 1;
    const int wn   = warp & 1;
    const int row0 = blockIdx.y * 128;
    const int t    = blockIdx.x;
    const int c0   = t * 128;

    if (tid < 128) bias_s[tid] = bias[c0 + tid];

    const int grp = lane >> 3;
    const int lr  = lane & 7;

    unsigned aB[2], bB[2];
    #pragma unroll
    for (int s = 0; s < 2; s++) {
        aB[s] = smem_u32(&As[s][0]) +
                ((unsigned)((wm * 32 + (grp & 1) * 8 + lr) * PA + (grp >> 1) * 4) << 2);
        bB[s] = smem_u32(&Bs[s][0]) +
                ((unsigned)((wn * 64 + (grp >> 1) * 8 + lr) * PA + (grp & 1) * 4) << 2);
    }

    // Loader thread mapping: chunk c = it*256+tid, row = c>>2, k-octet = (c&3)*8.
    const int lm = tid >> 2;            // rows 0..63 (it adds +64)
    const int lk = (tid & 3) * 8;       // k offset in halves

    uint4 aSt[2], bSt[2];
    auto fetch = [&](int k0) {
        #pragma unroll
        for (int it = 0; it < 2; it++) {
            int m = lm + it * 64;
            aSt[it] = *(const uint4*)(g_hid + (size_t)(row0 + m) * HID + k0 + lk);
            bSt[it] = *(const uint4*)(g_wb  + (size_t)(c0  + m) * HID + k0 + lk);
        }
    };
    auto commit = [&](int s) {
        #pragma unroll
        for (int it = 0; it < 2; it++) {
            int m = lm + it * 64;
            *(uint4*)&As[s][m * 2 * PA + lk] = aSt[it];
            *(uint4*)&Bs[s][m * 2 * PA + lk] = bSt[it];
        }
    };

    float acc[2][8][4] = {};

    fetch(0);
    commit(0);
    __syncthreads();

    const int NKT = HID / 32;   // 24
    for (int kt = 0; kt < NKT; kt++) {
        int cur = kt & 1;
        if (kt + 1 < NKT) fetch((kt + 1) * 32);

        #pragma unroll
        for (int ks = 0; ks < 2; ks++) {
            unsigned af0[4], af1[4];
            ldsm4(af0, aB[cur] + ks * 32);
            ldsm4(af1, aB[cur] + 16 * PA * 4 + ks * 32);
            unsigned bf[4][4];
            #pragma unroll
            for (int pr = 0; pr < 4; pr++)
                ldsm4(bf[pr], bB[cur] + pr * 16 * PA * 4 + ks * 32);
            #pragma unroll
            for (int ni = 0; ni < 8; ni++) {
                unsigned b0 = bf[ni >> 1][(ni & 1) * 2];
                unsigned b1 = bf[ni >> 1][(ni & 1) * 2 + 1];
                mma16816(acc[0][ni], af0[0], af0[1], af0[2], af0[3], b0, b1);
                mma16816(acc[1][ni], af1[0], af1[1], af1[2], af1[3], b0, b1);
            }
        }

        if (kt + 1 < NKT) commit(1 - cur);
        __syncthreads();
    }

    // Epilogue: bias + RoPE (interleaved pairs live in c-reg pairs), store bf16x2.
    const int r     = lane >> 2;
    const int cpair = 2 * (lane & 3);
    #pragma unroll
    for (int mi = 0; mi < 2; mi++) {
        #pragma unroll
        for (int half = 0; half < 2; half++) {
            int ml  = wm * 32 + mi * 16 + r + half * 8;
            int row = row0 + ml;
            int bb  = row >> 9;
            int s   = row & 511;
            #pragma unroll
            for (int ni = 0; ni < 8; ni++) {
                int cl = wn * 64 + ni * 8 + cpair;
                float xe = acc[mi][ni][half * 2 + 0] + bias_s[cl];
                float xo = acc[mi][ni][half * 2 + 1] + bias_s[cl + 1];
                int d = cl & 63;
                float cv = g_cs[(s << 6) + d];
                float sv = g_sn[(s << 6) + d];
                float ve = xe * cv - xo * sv;
                float vo = xo * cv + xe * sv;
                __nv_bfloat16* dst = ((cl < 64) ? g_q : g_k)
                                   + ((size_t)((bb * NT + t) * SEQ + s) << 6) + d;
                *reinterpret_cast<unsigned*>(dst) = pk(ve, vo);
            }
        }
    }
}

// ---------------------------------------------------------------------------
// Kernel 2: logits[b,t,m,n] = q . k over d=64, bf16 tensor cores,
// cp.async smem fill, ldmatrix fragments, fused mask/tril/scale epilogue.
// Fully-below-diagonal blocks (m0 >= n0+128) skip loads/MMA: every output
// there is (-(1-pm)*NEG - NEG)*0.125 plus an O(1) term that is ~1e-11
// relative — far below threshold — so we stream the mask-only value.
// Block 128x128, grid (4,4,144).
// ---------------------------------------------------------------------------
__global__ void __launch_bounds__(256) qk_kernel(
    const int* __restrict__ amask,
    float* __restrict__ out)
{
    __shared__ __align__(16) __nv_bfloat16 Qs[128 * 2 * PQ];
    __shared__ __align__(16) __nv_bfloat16 Ks[128 * 2 * PQ];
    __shared__ float pm_s[128];
    __shared__ float vcol[128];

    const int tid  = threadIdx.x;
    const int lane = tid & 31;
    const int warp = tid >> 5;
    const int wm   = warp >> 1;
    const int wn   = warp & 1;
    const int z    = blockIdx.z;          // b*9 + t
    const int bb   = z / NT;
    const int n0   = blockIdx.x * 128;
    const int m0   = blockIdx.y * 128;

    if (m0 >= n0 + 128) {
        // Entire tile strictly below the diagonal: mask-only fast path.
        if (tid < 128) {
            float p = (float)amask[(bb << 9) + n0 + tid];
            vcol[tid] = (-(1.0f - p) * NEGC - NEGC) * 0.125f;
        }
        __syncthreads();
        const int ncol = (tid & 31) * 4;
        float4 o;
        o.x = vcol[ncol];     o.y = vcol[ncol + 1];
        o.z = vcol[ncol + 2]; o.w = vcol[ncol + 3];
        const int rbase = tid >> 5;
        #pragma unroll
        for (int r = 0; r < 16; r++) {
            int m = m0 + rbase + r * 8;
            *(float4*)(out + ((size_t)z * SEQ + m) * SEQ + n0 + ncol) = o;
        }
        return;
    }

    // Async 16B copies: Q/K tiles are raw bf16 moves.
    #pragma unroll
    for (int it = 0; it < 4; it++) {
        int idx = it * 256 + tid;
        int m = idx >> 3, c = (idx & 7) * 8;
        unsigned dq = smem_u32(&Qs[m * 2 * PQ + c]);
        const __nv_bfloat16* sq = g_q + ((size_t)(z * SEQ + m0 + m) << 6) + c;
        asm volatile("cp.async.cg.shared.global [%0], [%1], 16;" :: "r"(dq), "l"(sq));
        unsigned dk = smem_u32(&Ks[m * 2 * PQ + c]);
        const __nv_bfloat16* sk = g_k + ((size_t)(z * SEQ + n0 + m) << 6) + c;
        asm volatile("cp.async.cg.shared.global [%0], [%1], 16;" :: "r"(dk), "l"(sk));
    }
    asm volatile("cp.async.commit_group;");
    if (tid < 128) pm_s[tid] = (float)amask[(bb << 9) + n0 + tid];
    asm volatile("cp.async.wait_group 0;");
    __syncthreads();

    const int grp = lane >> 3;
    const int lr  = lane & 7;
    unsigned aBase = smem_u32(&Qs[0]) +
                     ((unsigned)((wm * 32 + (grp & 1) * 8 + lr) * PQ + (grp >> 1) * 4) << 2);
    unsigned bBase = smem_u32(&Ks[0]) +
                     ((unsigned)((wn * 64 + (grp >> 1) * 8 + lr) * PQ + (grp & 1) * 4) << 2);

    float acc[2][8][4] = {};
    #pragma unroll
    for (int ks = 0; ks < 4; ks++) {
        unsigned af0[4], af1[4];
        ldsm4(af0, aBase + ks * 32);
        ldsm4(af1, aBase + 16 * PQ * 4 + ks * 32);
        unsigned bf[4][4];
        #pragma unroll
        for (int pr = 0; pr < 4; pr++)
            ldsm4(bf[pr], bBase + pr * 16 * PQ * 4 + ks * 32);
        #pragma unroll
        for (int ni = 0; ni < 8; ni++) {
            unsigned b0 = bf[ni >> 1][(ni & 1) * 2];
            unsigned b1 = bf[ni >> 1][(ni & 1) * 2 + 1];
            mma16816(acc[0][ni], af0[0], af0[1], af0[2], af0[3], b0, b1);
            mma16816(acc[1][ni], af1[0], af1[1], af1[2], af1[3], b0, b1);
        }
    }

    // Epilogue: padding mask, strict-lower-tril, /8.
    const int r     = lane >> 2;
    const int cpair = 2 * (lane & 3);
    #pragma unroll
    for (int mi = 0; mi < 2; mi++) {
        #pragma unroll
        for (int half = 0; half < 2; half++) {
            int m = m0 + wm * 32 + mi * 16 + r + half * 8;
            #pragma unroll
            for (int ni = 0; ni < 8; ni++) {
                int nl = wn * 64 + ni * 8 + cpair;
                int n  = n0 + nl;
                float p0 = pm_s[nl], p1 = pm_s[nl + 1];
                float v0 = acc[mi][ni][half * 2 + 0] * p0 - (1.0f - p0) * NEGC;
                float v1 = acc[mi][ni][half * 2 + 1] * p1 - (1.0f - p1) * NEGC;
                if (m > n)     v0 -= NEGC;
                if (m > n + 1) v1 -= NEGC;
                v0 *= 0.125f;
                v1 *= 0.125f;
                *(float2*)(out + ((size_t)z * SEQ + m) * SEQ + n) = make_float2(v0, v1);
            }
        }
    }
}

// ---------------------------------------------------------------------------
extern "C" void kernel_launch(void* const* d_in, const int* in_sizes, int n_in,
                              void* d_out, int out_size)
{
    const float* hidden = (const float*)d_in[0];
    const float* Wm     = (const float*)d_in[1];
    const float* bias   = (const float*)d_in[2];
    const int*   amask  = (const int*)d_in[3];
    float* out = (float*)d_out;

    prep<<<PREP_TOT / 256, 256>>>(hidden, Wm);
    gemm_rope<<<dim3(COUT / 128, MROWS / 128), 256>>>(bias);
    qk_kernel<<<dim3(SEQ / 128, SEQ / 128, BATCH * NT), 256>>>(amask, out);
}

// round 13
// speedup vs baseline: 5.2565x; 1.1945x over previous
#include <cuda_runtime.h>
#include <cuda_bf16.h>
#include <math.h>

// Problem constants
#define BATCH 16
#define SEQ   512
#define HID   768
#define NT    9
#define DIM   64
#define COUT  (NT * 2 * DIM)   // 1152
#define MROWS (BATCH * SEQ)    // 8192
#define NEGC  1000000000000.0f

#define PA 20   // smem pitch in 32-bit words, gemm tiles (40 halves = 80 B)
#define PQ 36   // smem pitch in 32-bit words, qk tiles (72 halves = 144 B)
#define STG 3   // gemm smem pipeline stages
#define STAGE_HALVES (128 * 2 * PA)            // 5120 halves per operand stage
#define GEMM_DSMEM (STG * 2 * STAGE_HALVES * 2) // 61440 bytes

// Scratch (device globals — no allocation allowed in kernel_launch)
__device__ __align__(16) __nv_bfloat16 g_q[BATCH * NT * SEQ * DIM];   // [b,t,s,d]
__device__ __align__(16) __nv_bfloat16 g_k[BATCH * NT * SEQ * DIM];   // [b,t,s,d]
__device__ __align__(16) __nv_bfloat16 g_hid[MROWS * HID];            // bf16 hidden [m][k]
__device__ __align__(16) __nv_bfloat16 g_wb[COUT * HID];              // bf16 W^T [n][k]
__device__ float g_cs[SEQ * DIM];
__device__ float g_sn[SEQ * DIM];

// ---------------------------------------------------------------------------
// Helpers
// ---------------------------------------------------------------------------
__device__ __forceinline__ unsigned pk(float lo, float hi) {
    __nv_bfloat162 h = __float22bfloat162_rn(make_float2(lo, hi));
    return *reinterpret_cast<unsigned*>(&h);
}

__device__ __forceinline__ unsigned smem_u32(const void* p) {
    return (unsigned)__cvta_generic_to_shared(p);
}

__device__ __forceinline__ void ldsm4(unsigned r[4], unsigned addr) {
    asm volatile("ldmatrix.sync.aligned.m8n8.x4.shared.b16 {%0,%1,%2,%3}, [%4];"
                 : "=r"(r[0]), "=r"(r[1]), "=r"(r[2]), "=r"(r[3]) : "r"(addr));
}

__device__ __forceinline__ void cpasync16(unsigned dst, const void* src) {
    asm volatile("cp.async.cg.shared.global [%0], [%1], 16;" :: "r"(dst), "l"(src));
}

__device__ __forceinline__ void mma16816(float* c,
    unsigned a0, unsigned a1, unsigned a2, unsigned a3,
    unsigned b0, unsigned b1)
{
    asm volatile(
        "mma.sync.aligned.m16n8k16.row.col.f32.bf16.bf16.f32 "
        "{%0,%1,%2,%3},{%4,%5,%6,%7},{%8,%9},{%0,%1,%2,%3};\n"
        : "+f"(c[0]), "+f"(c[1]), "+f"(c[2]), "+f"(c[3])
        : "r"(a0), "r"(a1), "r"(a2), "r"(a3), "r"(b0), "r"(b1));
}

// ---------------------------------------------------------------------------
// Kernel 0 (prep): hidden -> bf16, W -> bf16 transposed [n][k], RoPE tables.
// ---------------------------------------------------------------------------
#define HQ (MROWS * HID / 4)
#define WQ (COUT * HID / 4)
#define PREP_TOT (HQ + WQ + SEQ * DIM)   // 1,826,816 = 7136 * 256

__global__ void __launch_bounds__(256) prep(
    const float* __restrict__ hidden,
    const float* __restrict__ Wm)
{
    int idx = blockIdx.x * blockDim.x + threadIdx.x;
    if (idx < HQ) {
        float4 v = ((const float4*)hidden)[idx];
        uint2 o = make_uint2(pk(v.x, v.y), pk(v.z, v.w));
        *reinterpret_cast<uint2*>(g_hid + (size_t)idx * 4) = o;
    } else if (idx < HQ + WQ) {
        int j  = idx - HQ;
        int n  = j % COUT;
        int kq = j / COUT;
        int k  = kq * 4;
        float a = Wm[(size_t)(k + 0) * COUT + n];
        float b = Wm[(size_t)(k + 1) * COUT + n];
        float c = Wm[(size_t)(k + 2) * COUT + n];
        float d = Wm[(size_t)(k + 3) * COUT + n];
        uint2 o = make_uint2(pk(a, b), pk(c, d));
        *reinterpret_cast<uint2*>(g_wb + (size_t)n * HID + k) = o;
    } else if (idx < PREP_TOT) {
        int e = idx - HQ - WQ;
        int s = e >> 6, d = e & 63, i = d >> 1;
        float inv = powf(10000.0f, -(float)(2 * i) / 64.0f);
        float ang = (float)s * inv;
        g_cs[e] = cosf(ang);
        g_sn[e] = sinf(ang);
    }
}

// ---------------------------------------------------------------------------
// Kernel 1: bf16 tensor-core GEMM  out[8192,1152] = hidden @ W + b,
// fused RoPE epilogue, scatter into g_q / g_k (bf16, [b,t,s,d]).
// Block 128x128, K-tile 32, 256 threads, warps 4x2.
// 3-stage cp.async smem ring (dynamic smem), ldmatrix fragments,
// one __syncthreads per K-tile.
// ---------------------------------------------------------------------------
__global__ void __launch_bounds__(256) gemm_rope(const float* __restrict__ bias)
{
    extern __shared__ __align__(16) char dyn[];
    __nv_bfloat16* As = reinterpret_cast<__nv_bfloat16*>(dyn);
    __nv_bfloat16* Bs = As + STG * STAGE_HALVES;
    __shared__ float bias_s[128];

    const int tid  = threadIdx.x;
    const int lane = tid & 31;
    const int warp = tid >> 5;
    const int wm   = warp >> 1;
    const int wn   = warp & 1;
    const int row0 = blockIdx.y * 128;
    const int t    = blockIdx.x;
    const int c0   = t * 128;

    if (tid < 128) bias_s[tid] = bias[c0 + tid];

    const int grp = lane >> 3;
    const int lr  = lane & 7;

    unsigned aB[STG], bB[STG];
    #pragma unroll
    for (int s = 0; s < STG; s++) {
        aB[s] = smem_u32(As + s * STAGE_HALVES) +
                ((unsigned)((wm * 32 + (grp & 1) * 8 + lr) * PA + (grp >> 1) * 4) << 2);
        bB[s] = smem_u32(Bs + s * STAGE_HALVES) +
                ((unsigned)((wn * 64 + (grp >> 1) * 8 + lr) * PA + (grp & 1) * 4) << 2);
    }

    // Loader thread mapping: 16B chunk per thread per half-tile.
    const int lm = tid >> 2;            // rows 0..63 (+64 on second it)
    const int lk = (tid & 3) * 8;       // k offset in halves

    auto issue = [&](int kt) {
        int s  = kt % STG;
        int k0 = kt * 32;
        #pragma unroll
        for (int it = 0; it < 2; it++) {
            int m = lm + it * 64;
            cpasync16(smem_u32(As + s * STAGE_HALVES + m * 2 * PA + lk),
                      g_hid + (size_t)(row0 + m) * HID + k0 + lk);
            cpasync16(smem_u32(Bs + s * STAGE_HALVES + m * 2 * PA + lk),
                      g_wb  + (size_t)(c0  + m) * HID + k0 + lk);
        }
        asm volatile("cp.async.commit_group;");
    };

    float acc[2][8][4] = {};

    const int NKT = HID / 32;   // 24
    issue(0);
    issue(1);

    for (int kt = 0; kt < NKT; kt++) {
        if (kt == NKT - 1) asm volatile("cp.async.wait_group 0;");
        else               asm volatile("cp.async.wait_group 1;");
        __syncthreads();
        if (kt + 2 < NKT) issue(kt + 2);

        int cur = kt % STG;
        #pragma unroll
        for (int ks = 0; ks < 2; ks++) {
            unsigned af0[4], af1[4];
            ldsm4(af0, aB[cur] + ks * 32);
            ldsm4(af1, aB[cur] + 16 * PA * 4 + ks * 32);
            unsigned bf[4][4];
            #pragma unroll
            for (int pr = 0; pr < 4; pr++)
                ldsm4(bf[pr], bB[cur] + pr * 16 * PA * 4 + ks * 32);
            #pragma unroll
            for (int ni = 0; ni < 8; ni++) {
                unsigned b0 = bf[ni >> 1][(ni & 1) * 2];
                unsigned b1 = bf[ni >> 1][(ni & 1) * 2 + 1];
                mma16816(acc[0][ni], af0[0], af0[1], af0[2], af0[3], b0, b1);
                mma16816(acc[1][ni], af1[0], af1[1], af1[2], af1[3], b0, b1);
            }
        }
    }

    // Epilogue: bias + RoPE (interleaved pairs live in c-reg pairs), store bf16x2.
    const int r     = lane >> 2;
    const int cpair = 2 * (lane & 3);
    #pragma unroll
    for (int mi = 0; mi < 2; mi++) {
        #pragma unroll
        for (int half = 0; half < 2; half++) {
            int ml  = wm * 32 + mi * 16 + r + half * 8;
            int row = row0 + ml;
            int bb  = row >> 9;
            int s   = row & 511;
            #pragma unroll
            for (int ni = 0; ni < 8; ni++) {
                int cl = wn * 64 + ni * 8 + cpair;
                float xe = acc[mi][ni][half * 2 + 0] + bias_s[cl];
                float xo = acc[mi][ni][half * 2 + 1] + bias_s[cl + 1];
                int d = cl & 63;
                float cv = g_cs[(s << 6) + d];
                float sv = g_sn[(s << 6) + d];
                float ve = xe * cv - xo * sv;
                float vo = xo * cv + xe * sv;
                __nv_bfloat16* dst = ((cl < 64) ? g_q : g_k)
                                   + ((size_t)((bb * NT + t) * SEQ + s) << 6) + d;
                *reinterpret_cast<unsigned*>(dst) = pk(ve, vo);
            }
        }
    }
}

// ---------------------------------------------------------------------------
// Kernel 2: logits[b,t,m,n] = q . k over d=64, bf16 tensor cores,
// cp.async smem fill, ldmatrix fragments, fused mask/tril/scale epilogue.
// Fully-below-diagonal blocks stream the mask-only value (O(1) vs 1e12
// perturbation, ~1e-11 relative — far below threshold).
// Block 128x128, grid (4,4,144).
// ---------------------------------------------------------------------------
__global__ void __launch_bounds__(256) qk_kernel(
    const int* __restrict__ amask,
    float* __restrict__ out)
{
    __shared__ __align__(16) __nv_bfloat16 Qs[128 * 2 * PQ];
    __shared__ __align__(16) __nv_bfloat16 Ks[128 * 2 * PQ];
    __shared__ float pm_s[128];
    __shared__ float vcol[128];

    const int tid  = threadIdx.x;
    const int lane = tid & 31;
    const int warp = tid >> 5;
    const int wm   = warp >> 1;
    const int wn   = warp & 1;
    const int z    = blockIdx.z;          // b*9 + t
    const int bb   = z / NT;
    const int n0   = blockIdx.x * 128;
    const int m0   = blockIdx.y * 128;

    if (m0 >= n0 + 128) {
        if (tid < 128) {
            float p = (float)amask[(bb << 9) + n0 + tid];
            vcol[tid] = (-(1.0f - p) * NEGC - NEGC) * 0.125f;
        }
        __syncthreads();
        const int ncol = (tid & 31) * 4;
        float4 o;
        o.x = vcol[ncol];     o.y = vcol[ncol + 1];
        o.z = vcol[ncol + 2]; o.w = vcol[ncol + 3];
        const int rbase = tid >> 5;
        #pragma unroll
        for (int r = 0; r < 16; r++) {
            int m = m0 + rbase + r * 8;
            *(float4*)(out + ((size_t)z * SEQ + m) * SEQ + n0 + ncol) = o;
        }
        return;
    }

    #pragma unroll
    for (int it = 0; it < 4; it++) {
        int idx = it * 256 + tid;
        int m = idx >> 3, c = (idx & 7) * 8;
        cpasync16(smem_u32(&Qs[m * 2 * PQ + c]),
                  g_q + ((size_t)(z * SEQ + m0 + m) << 6) + c);
        cpasync16(smem_u32(&Ks[m * 2 * PQ + c]),
                  g_k + ((size_t)(z * SEQ + n0 + m) << 6) + c);
    }
    asm volatile("cp.async.commit_group;");
    if (tid < 128) pm_s[tid] = (float)amask[(bb << 9) + n0 + tid];
    asm volatile("cp.async.wait_group 0;");
    __syncthreads();

    const int grp = lane >> 3;
    const int lr  = lane & 7;
    unsigned aBase = smem_u32(&Qs[0]) +
                     ((unsigned)((wm * 32 + (grp & 1) * 8 + lr) * PQ + (grp >> 1) * 4) << 2);
    unsigned bBase = smem_u32(&Ks[0]) +
                     ((unsigned)((wn * 64 + (grp >> 1) * 8 + lr) * PQ + (grp & 1) * 4) << 2);

    float acc[2][8][4] = {};
    #pragma unroll
    for (int ks = 0; ks < 4; ks++) {
        unsigned af0[4], af1[4];
        ldsm4(af0, aBase + ks * 32);
        ldsm4(af1, aBase + 16 * PQ * 4 + ks * 32);
        unsigned bf[4][4];
        #pragma unroll
        for (int pr = 0; pr < 4; pr++)
            ldsm4(bf[pr], bBase + pr * 16 * PQ * 4 + ks * 32);
        #pragma unroll
        for (int ni = 0; ni < 8; ni++) {
            unsigned b0 = bf[ni >> 1][(ni & 1) * 2];
            unsigned b1 = bf[ni >> 1][(ni & 1) * 2 + 1];
            mma16816(acc[0][ni], af0[0], af0[1], af0[2], af0[3], b0, b1);
            mma16816(acc[1][ni], af1[0], af1[1], af1[2], af1[3], b0, b1);
        }
    }

    const int r     = lane >> 2;
    const int cpair = 2 * (lane & 3);
    #pragma unroll
    for (int mi = 0; mi < 2; mi++) {
        #pragma unroll
        for (int half = 0; half < 2; half++) {
            int m = m0 + wm * 32 + mi * 16 + r + half * 8;
            #pragma unroll
            for (int ni = 0; ni < 8; ni++) {
                int nl = wn * 64 + ni * 8 + cpair;
                int n  = n0 + nl;
                float p0 = pm_s[nl], p1 = pm_s[nl + 1];
                float v0 = acc[mi][ni][half * 2 + 0] * p0 - (1.0f - p0) * NEGC;
                float v1 = acc[mi][ni][half * 2 + 1] * p1 - (1.0f - p1) * NEGC;
                if (m > n)     v0 -= NEGC;
                if (m > n + 1) v1 -= NEGC;
                v0 *= 0.125f;
                v1 *= 0.125f;
                *(float2*)(out + ((size_t)z * SEQ + m) * SEQ + n) = make_float2(v0, v1);
            }
        }
    }
}

// ---------------------------------------------------------------------------
extern "C" void kernel_launch(void* const* d_in, const int* in_sizes, int n_in,
                              void* d_out, int out_size)
{
    const float* hidden = (const float*)d_in[0];
    const float* Wm     = (const float*)d_in[1];
    const float* bias   = (const float*)d_in[2];
    const int*   amask  = (const int*)d_in[3];
    float* out = (float*)d_out;

    static bool attr_done = false;
    if (!attr_done) {
        cudaFuncSetAttribute(gemm_rope,
                             cudaFuncAttributeMaxDynamicSharedMemorySize,
                             GEMM_DSMEM);
        attr_done = true;
    }

    prep<<<PREP_TOT / 256, 256>>>(hidden, Wm);
    gemm_rope<<<dim3(COUT / 128, MROWS / 128), 256, GEMM_DSMEM>>>(bias);
    qk_kernel<<<dim3(SEQ / 128, SEQ / 128, BATCH * NT), 256>>>(amask, out);
}

// round 14
// speedup vs baseline: 5.3828x; 1.0240x over previous
#include <cuda_runtime.h>
#include <cuda_bf16.h>
#include <math.h>

// Problem constants
#define BATCH 16
#define SEQ   512
#define HID   768
#define NT    9
#define DIM   64
#define COUT  (NT * 2 * DIM)   // 1152
#define MROWS (BATCH * SEQ)    // 8192
#define NEGC  1000000000000.0f

#define PA 20   // smem pitch in 32-bit words, gemm tiles (40 halves = 80 B)
#define PQ 36   // smem pitch in 32-bit words, qk tiles (72 halves = 144 B)
#define STG 3   // gemm smem pipeline stages
#define STAGE_HALVES (128 * 2 * PA)             // 5120 halves per operand stage
#define GEMM_DSMEM (STG * 2 * STAGE_HALVES * 2) // 61440 bytes

// Scratch (device globals — no allocation allowed in kernel_launch)
__device__ __align__(16) __nv_bfloat16 g_q[BATCH * NT * SEQ * DIM];   // [b,t,s,d]
__device__ __align__(16) __nv_bfloat16 g_k[BATCH * NT * SEQ * DIM];   // [b,t,s,d]
__device__ __align__(16) __nv_bfloat16 g_hid[MROWS * HID];            // bf16 hidden [m][k]
__device__ __align__(16) __nv_bfloat16 g_wb[COUT * HID];              // bf16 W^T [n][k]
__device__ float g_cs[SEQ * DIM];
__device__ float g_sn[SEQ * DIM];

// ---------------------------------------------------------------------------
// Helpers
// ---------------------------------------------------------------------------
__device__ __forceinline__ unsigned pk(float lo, float hi) {
    __nv_bfloat162 h = __float22bfloat162_rn(make_float2(lo, hi));
    return *reinterpret_cast<unsigned*>(&h);
}

__device__ __forceinline__ unsigned smem_u32(const void* p) {
    return (unsigned)__cvta_generic_to_shared(p);
}

__device__ __forceinline__ void ldsm4(unsigned r[4], unsigned addr) {
    asm volatile("ldmatrix.sync.aligned.m8n8.x4.shared.b16 {%0,%1,%2,%3}, [%4];"
                 : "=r"(r[0]), "=r"(r[1]), "=r"(r[2]), "=r"(r[3]) : "r"(addr));
}

__device__ __forceinline__ void cpasync16(unsigned dst, const void* src) {
    asm volatile("cp.async.cg.shared.global [%0], [%1], 16;" :: "r"(dst), "l"(src));
}

__device__ __forceinline__ void stg_cs_f2(float* p, float a, float b) {
    asm volatile("st.global.cs.v2.f32 [%0], {%1,%2};"
                 :: "l"(p), "f"(a), "f"(b) : "memory");
}

__device__ __forceinline__ void stg_cs_f4(float* p, float4 v) {
    asm volatile("st.global.cs.v4.f32 [%0], {%1,%2,%3,%4};"
                 :: "l"(p), "f"(v.x), "f"(v.y), "f"(v.z), "f"(v.w) : "memory");
}

__device__ __forceinline__ void mma16816(float* c,
    unsigned a0, unsigned a1, unsigned a2, unsigned a3,
    unsigned b0, unsigned b1)
{
    asm volatile(
        "mma.sync.aligned.m16n8k16.row.col.f32.bf16.bf16.f32 "
        "{%0,%1,%2,%3},{%4,%5,%6,%7},{%8,%9},{%0,%1,%2,%3};\n"
        : "+f"(c[0]), "+f"(c[1]), "+f"(c[2]), "+f"(c[3])
        : "r"(a0), "r"(a1), "r"(a2), "r"(a3), "r"(b0), "r"(b1));
}

// ---------------------------------------------------------------------------
// Kernel 0 (prep): hidden -> bf16, W -> bf16 transposed [n][k], RoPE tables.
// ---------------------------------------------------------------------------
#define HQ (MROWS * HID / 4)
#define WQ (COUT * HID / 4)
#define PREP_TOT (HQ + WQ + SEQ * DIM)   // 1,826,816 = 7136 * 256

__global__ void __launch_bounds__(256) prep(
    const float* __restrict__ hidden,
    const float* __restrict__ Wm)
{
    int idx = blockIdx.x * blockDim.x + threadIdx.x;
    if (idx < HQ) {
        float4 v = ((const float4*)hidden)[idx];
        uint2 o = make_uint2(pk(v.x, v.y), pk(v.z, v.w));
        *reinterpret_cast<uint2*>(g_hid + (size_t)idx * 4) = o;
    } else if (idx < HQ + WQ) {
        int j  = idx - HQ;
        int n  = j % COUT;
        int kq = j / COUT;
        int k  = kq * 4;
        float a = Wm[(size_t)(k + 0) * COUT + n];
        float b = Wm[(size_t)(k + 1) * COUT + n];
        float c = Wm[(size_t)(k + 2) * COUT + n];
        float d = Wm[(size_t)(k + 3) * COUT + n];
        uint2 o = make_uint2(pk(a, b), pk(c, d));
        *reinterpret_cast<uint2*>(g_wb + (size_t)n * HID + k) = o;
    } else if (idx < PREP_TOT) {
        int e = idx - HQ - WQ;
        int s = e >> 6, d = e & 63, i = d >> 1;
        float inv = powf(10000.0f, -(float)(2 * i) / 64.0f);
        float ang = (float)s * inv;
        g_cs[e] = cosf(ang);
        g_sn[e] = sinf(ang);
    }
}

// ---------------------------------------------------------------------------
// Kernel 1: bf16 tensor-core GEMM  out[8192,1152] = hidden @ W + b,
// fused RoPE epilogue, scatter into g_q / g_k (bf16, [b,t,s,d]).
// Block 128x128, K-tile 32, 256 threads, warps 4x2.
// 3-stage cp.async smem ring, ldmatrix fragments, 2 CTAs/SM (reg-capped).
// ---------------------------------------------------------------------------
__global__ void __launch_bounds__(256, 2) gemm_rope(const float* __restrict__ bias)
{
    extern __shared__ __align__(16) char dyn[];
    __nv_bfloat16* As = reinterpret_cast<__nv_bfloat16*>(dyn);
    __nv_bfloat16* Bs = As + STG * STAGE_HALVES;
    __shared__ float bias_s[128];

    const int tid  = threadIdx.x;
    const int lane = tid & 31;
    const int warp = tid >> 5;
    const int wm   = warp >> 1;
    const int wn   = warp & 1;
    const int row0 = blockIdx.y * 128;
    const int t    = blockIdx.x;
    const int c0   = t * 128;

    if (tid < 128) bias_s[tid] = bias[c0 + tid];

    const int grp = lane >> 3;
    const int lr  = lane & 7;

    unsigned aB[STG], bB[STG];
    #pragma unroll
    for (int s = 0; s < STG; s++) {
        aB[s] = smem_u32(As + s * STAGE_HALVES) +
                ((unsigned)((wm * 32 + (grp & 1) * 8 + lr) * PA + (grp >> 1) * 4) << 2);
        bB[s] = smem_u32(Bs + s * STAGE_HALVES) +
                ((unsigned)((wn * 64 + (grp >> 1) * 8 + lr) * PA + (grp & 1) * 4) << 2);
    }

    const int lm = tid >> 2;            // rows 0..63 (+64 on second it)
    const int lk = (tid & 3) * 8;       // k offset in halves

    auto issue = [&](int kt) {
        int s  = kt % STG;
        int k0 = kt * 32;
        #pragma unroll
        for (int it = 0; it < 2; it++) {
            int m = lm + it * 64;
            cpasync16(smem_u32(As + s * STAGE_HALVES + m * 2 * PA + lk),
                      g_hid + (size_t)(row0 + m) * HID + k0 + lk);
            cpasync16(smem_u32(Bs + s * STAGE_HALVES + m * 2 * PA + lk),
                      g_wb  + (size_t)(c0  + m) * HID + k0 + lk);
        }
        asm volatile("cp.async.commit_group;");
    };

    float acc[2][8][4] = {};

    const int NKT = HID / 32;   // 24
    issue(0);
    issue(1);

    for (int kt = 0; kt < NKT; kt++) {
        if (kt == NKT - 1) asm volatile("cp.async.wait_group 0;");
        else               asm volatile("cp.async.wait_group 1;");
        __syncthreads();
        if (kt + 2 < NKT) issue(kt + 2);

        int cur = kt % STG;
        #pragma unroll
        for (int ks = 0; ks < 2; ks++) {
            unsigned af0[4], af1[4];
            ldsm4(af0, aB[cur] + ks * 32);
            ldsm4(af1, aB[cur] + 16 * PA * 4 + ks * 32);
            unsigned bf[4][4];
            #pragma unroll
            for (int pr = 0; pr < 4; pr++)
                ldsm4(bf[pr], bB[cur] + pr * 16 * PA * 4 + ks * 32);
            #pragma unroll
            for (int ni = 0; ni < 8; ni++) {
                unsigned b0 = bf[ni >> 1][(ni & 1) * 2];
                unsigned b1 = bf[ni >> 1][(ni & 1) * 2 + 1];
                mma16816(acc[0][ni], af0[0], af0[1], af0[2], af0[3], b0, b1);
                mma16816(acc[1][ni], af1[0], af1[1], af1[2], af1[3], b0, b1);
            }
        }
    }

    // Epilogue: bias + RoPE (interleaved pairs live in c-reg pairs), store bf16x2.
    const int r     = lane >> 2;
    const int cpair = 2 * (lane & 3);
    #pragma unroll
    for (int mi = 0; mi < 2; mi++) {
        #pragma unroll
        for (int half = 0; half < 2; half++) {
            int ml  = wm * 32 + mi * 16 + r + half * 8;
            int row = row0 + ml;
            int bb  = row >> 9;
            int s   = row & 511;
            #pragma unroll
            for (int ni = 0; ni < 8; ni++) {
                int cl = wn * 64 + ni * 8 + cpair;
                float xe = acc[mi][ni][half * 2 + 0] + bias_s[cl];
                float xo = acc[mi][ni][half * 2 + 1] + bias_s[cl + 1];
                int d = cl & 63;
                float cv = g_cs[(s << 6) + d];
                float sv = g_sn[(s << 6) + d];
                float ve = xe * cv - xo * sv;
                float vo = xo * cv + xe * sv;
                __nv_bfloat16* dst = ((cl < 64) ? g_q : g_k)
                                   + ((size_t)((bb * NT + t) * SEQ + s) << 6) + d;
                *reinterpret_cast<unsigned*>(dst) = pk(ve, vo);
            }
        }
    }
}

// ---------------------------------------------------------------------------
// Kernel 2: logits[b,t,m,n] = q . k over d=64, bf16 tensor cores,
// cp.async smem fill, ldmatrix fragments, fused mask/tril/scale epilogue.
// Fully-below-diagonal blocks stream the mask-only value (~1e-11 relative
// perturbation — far below threshold). Streaming (.cs) stores throughout.
// Block 128x128, grid (4,4,144), 2 CTAs/SM.
// ---------------------------------------------------------------------------
__global__ void __launch_bounds__(256, 2) qk_kernel(
    const int* __restrict__ amask,
    float* __restrict__ out)
{
    __shared__ __align__(16) __nv_bfloat16 Qs[128 * 2 * PQ];
    __shared__ __align__(16) __nv_bfloat16 Ks[128 * 2 * PQ];
    __shared__ float pm_s[128];
    __shared__ float vcol[128];

    const int tid  = threadIdx.x;
    const int lane = tid & 31;
    const int warp = tid >> 5;
    const int wm   = warp >> 1;
    const int wn   = warp & 1;
    const int z    = blockIdx.z;          // b*9 + t
    const int bb   = z / NT;
    const int n0   = blockIdx.x * 128;
    const int m0   = blockIdx.y * 128;

    if (m0 >= n0 + 128) {
        if (tid < 128) {
            float p = (float)amask[(bb << 9) + n0 + tid];
            vcol[tid] = (-(1.0f - p) * NEGC - NEGC) * 0.125f;
        }
        __syncthreads();
        const int ncol = (tid & 31) * 4;
        float4 o;
        o.x = vcol[ncol];     o.y = vcol[ncol + 1];
        o.z = vcol[ncol + 2]; o.w = vcol[ncol + 3];
        const int rbase = tid >> 5;
        #pragma unroll
        for (int r = 0; r < 16; r++) {
            int m = m0 + rbase + r * 8;
            stg_cs_f4(out + ((size_t)z * SEQ + m) * SEQ + n0 + ncol, o);
        }
        return;
    }

    #pragma unroll
    for (int it = 0; it < 4; it++) {
        int idx = it * 256 + tid;
        int m = idx >> 3, c = (idx & 7) * 8;
        cpasync16(smem_u32(&Qs[m * 2 * PQ + c]),
                  g_q + ((size_t)(z * SEQ + m0 + m) << 6) + c);
        cpasync16(smem_u32(&Ks[m * 2 * PQ + c]),
                  g_k + ((size_t)(z * SEQ + n0 + m) << 6) + c);
    }
    asm volatile("cp.async.commit_group;");
    if (tid < 128) pm_s[tid] = (float)amask[(bb << 9) + n0 + tid];
    asm volatile("cp.async.wait_group 0;");
    __syncthreads();

    const int grp = lane >> 3;
    const int lr  = lane & 7;
    unsigned aBase = smem_u32(&Qs[0]) +
                     ((unsigned)((wm * 32 + (grp & 1) * 8 + lr) * PQ + (grp >> 1) * 4) << 2);
    unsigned bBase = smem_u32(&Ks[0]) +
                     ((unsigned)((wn * 64 + (grp >> 1) * 8 + lr) * PQ + (grp & 1) * 4) << 2);

    float acc[2][8][4] = {};
    #pragma unroll
    for (int ks = 0; ks < 4; ks++) {
        unsigned af0[4], af1[4];
        ldsm4(af0, aBase + ks * 32);
        ldsm4(af1, aBase + 16 * PQ * 4 + ks * 32);
        unsigned bf[4][4];
        #pragma unroll
        for (int pr = 0; pr < 4; pr++)
            ldsm4(bf[pr], bBase + pr * 16 * PQ * 4 + ks * 32);
        #pragma unroll
        for (int ni = 0; ni < 8; ni++) {
            unsigned b0 = bf[ni >> 1][(ni & 1) * 2];
            unsigned b1 = bf[ni >> 1][(ni & 1) * 2 + 1];
            mma16816(acc[0][ni], af0[0], af0[1], af0[2], af0[3], b0, b1);
            mma16816(acc[1][ni], af1[0], af1[1], af1[2], af1[3], b0, b1);
        }
    }

    const int r     = lane >> 2;
    const int cpair = 2 * (lane & 3);
    #pragma unroll
    for (int mi = 0; mi < 2; mi++) {
        #pragma unroll
        for (int half = 0; half < 2; half++) {
            int m = m0 + wm * 32 + mi * 16 + r + half * 8;
            #pragma unroll
            for (int ni = 0; ni < 8; ni++) {
                int nl = wn * 64 + ni * 8 + cpair;
                int n  = n0 + nl;
                float p0 = pm_s[nl], p1 = pm_s[nl + 1];
                float v0 = acc[mi][ni][half * 2 + 0] * p0 - (1.0f - p0) * NEGC;
                float v1 = acc[mi][ni][half * 2 + 1] * p1 - (1.0f - p1) * NEGC;
                if (m > n)     v0 -= NEGC;
                if (m > n + 1) v1 -= NEGC;
                v0 *= 0.125f;
                v1 *= 0.125f;
                stg_cs_f2(out + ((size_t)z * SEQ + m) * SEQ + n, v0, v1);
            }
        }
    }
}

// ---------------------------------------------------------------------------
extern "C" void kernel_launch(void* const* d_in, const int* in_sizes, int n_in,
                              void* d_out, int out_size)
{
    const float* hidden = (const float*)d_in[0];
    const float* Wm     = (const float*)d_in[1];
    const float* bias   = (const float*)d_in[2];
    const int*   amask  = (const int*)d_in[3];
    float* out = (float*)d_out;

    static bool attr_done = false;
    if (!attr_done) {
        cudaFuncSetAttribute(gemm_rope,
                             cudaFuncAttributeMaxDynamicSharedMemorySize,
                             GEMM_DSMEM);
        attr_done = true;
    }

    prep<<<PREP_TOT / 256, 256>>>(hidden, Wm);
    gemm_rope<<<dim3(COUT / 128, MROWS / 128), 256, GEMM_DSMEM>>>(bias);
    qk_kernel<<<dim3(SEQ / 128, SEQ / 128, BATCH * NT), 256>>>(amask, out);
}